// round 14
// baseline (speedup 1.0000x reference)
#include <cuda_runtime.h>
#include <cuda_bf16.h>
#include <cstdint>

typedef unsigned long long u64;

#define NSMAX 131072
__device__ float g_p2[54 * NSMAX];    // conv2+pool output [k][sample]

__device__ __forceinline__ u64 dup2(float a) {
    u64 r; asm("mov.b64 %0, {%1, %1};" : "=l"(r) : "r"(__float_as_uint(a))); return r;
}
__device__ __forceinline__ u64 pack2(float lo, float hi) {
    u64 r; asm("mov.b64 %0, {%1, %2};" : "=l"(r) : "r"(__float_as_uint(lo)), "r"(__float_as_uint(hi))); return r;
}
__device__ __forceinline__ void fma2(u64& acc, u64 a, u64 b) {
    asm("fma.rn.f32x2 %0, %1, %2, %0;" : "+l"(acc) : "l"(a), "l"(b));
}
__device__ __forceinline__ float2 unpack2(u64 v) {
    unsigned lo, hi; asm("mov.b64 {%0, %1}, %2;" : "=r"(lo), "=r"(hi) : "l"(v));
    return make_float2(__uint_as_float(lo), __uint_as_float(hi));
}

// ================================================================
// Kernel A: fused conv1+pool+relu+conv2+pool+relu -> g_p2
// c1 pooled rows live in a 4-row register ring (constant indices)
// ws: c1w[0..26] c1b[27..29] c2w[30..191] c2b[192..197]
// ================================================================
#define CF_TPB 128
#define CF_XS 129
#define CF_SMEM (128 * CF_XS * 4)

template<int PY, int SLOT>
__device__ __forceinline__ void c1row(float (&c1r)[4][18], const float* __restrict__ xp,
                                      const float* __restrict__ ws)
{
    float r[4][14];
#pragma unroll
    for (int j = 0; j < 4; j++) {
        const int rr = 2 * PY - 1 + j;
        r[j][0] = 0.0f; r[j][13] = 0.0f;
        if (rr < 0 || rr >= 11) {
#pragma unroll
            for (int c = 0; c < 12; c++) r[j][1 + c] = 0.0f;
        } else if (rr == 10) {
#pragma unroll
            for (int c = 0; c < 8; c++) r[j][1 + c] = xp[120 + c];
            r[j][9] = 0.0f; r[j][10] = 0.0f; r[j][11] = 0.0f; r[j][12] = 0.0f;
        } else {
#pragma unroll
            for (int c = 0; c < 12; c++) r[j][1 + c] = xp[12 * rr + c];
        }
    }
#pragma unroll
    for (int oc = 0; oc < 3; oc++) {
        float v0[12], v1[12];
#pragma unroll
        for (int cx = 0; cx < 12; cx++) {
            float a0 = 0.0f, a1 = 0.0f;
#pragma unroll
            for (int ky = 0; ky < 3; ky++) {
#pragma unroll
                for (int kx = 0; kx < 3; kx++) {
                    const float w = ws[oc * 9 + ky * 3 + kx];
                    a0 = fmaf(w, r[ky][cx + kx],     a0);
                    a1 = fmaf(w, r[ky + 1][cx + kx], a1);
                }
            }
            v0[cx] = a0; v1[cx] = a1;
        }
        const float bb = ws[27 + oc];
#pragma unroll
        for (int px = 0; px < 6; px++) {
            float m = fmaxf(fmaxf(v0[2 * px], v0[2 * px + 1]),
                            fmaxf(v1[2 * px], v1[2 * px + 1]));
            c1r[SLOT][oc * 6 + px] = fmaxf(m + bb, 0.0f);
        }
    }
}

template<int S>
__device__ __forceinline__ float rv(const float (&c1r)[4][18], int ic, int ix) {
    if constexpr (S < 0) return 0.0f;
    else return c1r[S][ic * 6 + ix];
}

// window rows (6x6 conv2 grid, pad 1): w0..w3 = c1 rows 2*PY2-1 .. 2*PY2+2 in slots SM1,S0,S1,S2
template<int PY2, int SM1, int S0, int S1, int S2>
__device__ __forceinline__ void band(const float (&c1r)[4][18], const float* __restrict__ ws,
                                     long long s)
{
#pragma unroll
    for (int oh = 0; oh < 2; oh++) {
        u64 acc[3][3][2];
#pragma unroll
        for (int q = 0; q < 3; q++)
#pragma unroll
            for (int px = 0; px < 3; px++) { acc[q][px][0] = 0ull; acc[q][px][1] = 0ull; }

#pragma unroll
        for (int ic = 0; ic < 3; ic++) {
            u64 pcp[3][8];   // pcp[j] = pack(window row j, window row j+1); padded cols 0,7
#pragma unroll
            for (int j = 0; j < 3; j++) {
                pcp[j][0] = 0ull; pcp[j][7] = 0ull;
#pragma unroll
                for (int ix = 0; ix < 6; ix++) {
                    const float lo = (j == 0) ? rv<SM1>(c1r, ic, ix)
                                   : (j == 1) ? rv<S0>(c1r, ic, ix)
                                              : rv<S1>(c1r, ic, ix);
                    const float hi = (j == 0) ? rv<S0>(c1r, ic, ix)
                                   : (j == 1) ? rv<S1>(c1r, ic, ix)
                                              : rv<S2>(c1r, ic, ix);
                    pcp[j][1 + ix] = pack2(lo, hi);
                }
            }
#pragma unroll
            for (int q = 0; q < 3; q++) {
                const int oc = oh * 3 + q;
#pragma unroll
                for (int ky = 0; ky < 3; ky++) {
#pragma unroll
                    for (int kx = 0; kx < 3; kx++) {
                        const u64 wd = dup2(ws[30 + oc * 27 + ic * 9 + ky * 3 + kx]);
#pragma unroll
                        for (int px = 0; px < 3; px++) {
                            fma2(acc[q][px][0], wd, pcp[ky][2 * px + kx]);
                            fma2(acc[q][px][1], wd, pcp[ky][2 * px + kx + 1]);
                        }
                    }
                }
            }
        }
#pragma unroll
        for (int q = 0; q < 3; q++) {
            const int oc = oh * 3 + q;
            const float bb = ws[192 + oc];
#pragma unroll
            for (int px = 0; px < 3; px++) {
                float2 v0 = unpack2(acc[q][px][0]), v1 = unpack2(acc[q][px][1]);
                float m = fmaxf(fmaxf(v0.x, v0.y), fmaxf(v1.x, v1.y));
                g_p2[(long long)(oc * 9 + PY2 * 3 + px) * NSMAX + s] = fmaxf(m + bb, 0.0f);
            }
        }
    }
}

__global__ void __launch_bounds__(CF_TPB, 3)
convf_kernel(const float* __restrict__ x,
             const float* __restrict__ c1w, const float* __restrict__ c1b,
             const float* __restrict__ c2w, const float* __restrict__ c2b,
             int nsamp)
{
    extern __shared__ float sx[];
    __shared__ float ws[200];
    const int tid = threadIdx.x;
    for (int i = tid; i < 27;  i += CF_TPB) ws[i]       = c1w[i];
    for (int i = tid; i < 3;   i += CF_TPB) ws[27 + i]  = c1b[i];
    for (int i = tid; i < 162; i += CF_TPB) ws[30 + i]  = c2w[i];
    for (int i = tid; i < 6;   i += CF_TPB) ws[192 + i] = c2b[i];

    const long long base = (long long)blockIdx.x * CF_TPB;

    // coalesced stage of x tile into smem (stride 129)
    for (int i = tid; i < 128 * 32; i += CF_TPB) {
        const int row = i >> 5, q = (i & 31) * 4;
        const long long s = base + row;
        float4 v = make_float4(0.f, 0.f, 0.f, 0.f);
        if (s < nsamp) v = *(const float4*)(x + s * 128 + q);
        float* d = sx + row * CF_XS + q;
        d[0] = v.x; d[1] = v.y; d[2] = v.z; d[3] = v.w;
    }
    __syncthreads();

    const long long s = base + tid;
    if (s >= nsamp) return;
    const float* xp = sx + tid * CF_XS;

    float c1r[4][18];

    c1row<0, 0>(c1r, xp, ws);
    c1row<1, 1>(c1r, xp, ws);
    c1row<2, 2>(c1r, xp, ws);
    band<0, -1, 0, 1, 2>(c1r, ws, s);     // c1 rows -,0,1,2
    c1row<3, 3>(c1r, xp, ws);
    c1row<4, 0>(c1r, xp, ws);             // overwrites dead row 0
    band<1, 1, 2, 3, 0>(c1r, ws, s);      // c1 rows 1,2,3,4
    c1row<5, 1>(c1r, xp, ws);             // overwrites dead row 1
    band<2, 3, 0, 1, -1>(c1r, ws, s);     // c1 rows 3,4,5,-
}

// ================================================================
// Kernel F: fused fc1+relu+out, chained mma.sync bf16 3-term split
// 512 threads; warp grid 4(m) x 4(n); warp tile m32 x n32  (round-11 proven)
// ================================================================
#define FK_TPB  512
#define F_B1   0
#define F_B2   512
#define F_W1H  1024
#define F_W1L  19456
#define F_W2H  37888
#define F_W2L  72704
#define F_P2H  107520
#define F_P2L  125952
#define F_HH   144384
#define F_HL   179200
#define F_D    144384
#define FK_SMEM 214016

#define LDSM_X4(r0, r1, r2, r3, addr) \
    asm volatile("ldmatrix.sync.aligned.m8n8.x4.shared.b16 {%0,%1,%2,%3}, [%4];" \
        : "=r"(r0), "=r"(r1), "=r"(r2), "=r"(r3) : "r"(addr))

#define MMA_BF16(c, a, b0, b1) \
    asm volatile("mma.sync.aligned.m16n8k16.row.col.f32.bf16.bf16.f32 " \
        "{%0,%1,%2,%3}, {%4,%5,%6,%7}, {%8,%9}, {%0,%1,%2,%3};" \
        : "+f"((c)[0]), "+f"((c)[1]), "+f"((c)[2]), "+f"((c)[3]) \
        : "r"((a)[0]), "r"((a)[1]), "r"((a)[2]), "r"((a)[3]), "r"(b0), "r"(b1))

__device__ __forceinline__ uint32_t smem_u32(const void* p) {
    uint32_t a;
    asm("{ .reg .u64 t; cvta.to.shared.u64 t, %1; cvt.u32.u64 %0, t; }" : "=r"(a) : "l"(p));
    return a;
}
__device__ __forceinline__ void bf16split(float f0, float f1, unsigned& hi, unsigned& lo) {
    asm("cvt.rn.bf16x2.f32 %0, %1, %2;" : "=r"(hi) : "f"(f1), "f"(f0));
    const float h0 = __uint_as_float(hi << 16);
    const float h1 = __uint_as_float(hi & 0xFFFF0000u);
    const float r0 = f0 - h0, r1 = f1 - h1;
    asm("cvt.rn.bf16x2.f32 %0, %1, %2;" : "=r"(lo) : "f"(r1), "f"(r0));
}
__device__ __forceinline__ void bf16split1(float v, unsigned short& hi, unsigned short& lo) {
    __nv_bfloat16 h = __float2bfloat16(v);
    float r = v - __bfloat162float(h);
    __nv_bfloat16 l = __float2bfloat16(r);
    hi = *(unsigned short*)&h;
    lo = *(unsigned short*)&l;
}

__global__ void __launch_bounds__(FK_TPB, 1)
head_kernel(const float* __restrict__ w1, const float* __restrict__ b1,
            const float* __restrict__ w2, const float* __restrict__ b2,
            float* __restrict__ out, int nsamp, int ntiles)
{
    extern __shared__ char smem[];
    const uint32_t sb = smem_u32(smem);
    const int tid = threadIdx.x;
    const int wid = tid >> 5, lid = tid & 31;

    if (tid < 128) { ((float*)(smem + F_B1))[tid] = b1[tid];
                     ((float*)(smem + F_B2))[tid] = b2[tid]; }
    for (int i = tid; i < 9216; i += FK_TPB) {
        ((uint32_t*)(smem + F_W1H))[i] = 0u;      // zero W1H+W1L (contiguous)
        ((uint32_t*)(smem + F_P2H))[i] = 0u;      // zero P2H+P2L (contiguous)
    }
    __syncthreads();
    if (tid < 128) {
        const int o = tid;
        const float* wr = w1 + o * 54;
        char* ah = smem + F_W1H + o * 144;
        char* al = smem + F_W1L + o * 144;
        for (int i = 0; i < 54; i += 2) {
            const float2 f = *(const float2*)(wr + i);
            unsigned h, l;
            bf16split(f.x, f.y, h, l);
            *(unsigned*)(ah + i * 2) = h;
            *(unsigned*)(al + i * 2) = l;
        }
    }
    {
        const int o  = tid & 127;
        const int kq = (tid >> 7) * 32;
        const float* wr = w2 + o * 128 + kq;
        char* ah = smem + F_W2H + o * 272 + kq * 2;
        char* al = smem + F_W2L + o * 272 + kq * 2;
        for (int i = 0; i < 32; i += 4) {
            const float4 f = *(const float4*)(wr + i);
            unsigned h0, l0, h1, l1;
            bf16split(f.x, f.y, h0, l0);
            bf16split(f.z, f.w, h1, l1);
            *(uint2*)(ah + i * 2) = make_uint2(h0, h1);
            *(uint2*)(al + i * 2) = make_uint2(l0, l1);
        }
    }

    const int mgrp = wid & 3;
    const int ngrp = wid >> 2;
    const int mbase0 = mgrp * 32;
    const int nbase  = ngrp * 32;
    const uint32_t ar = (uint32_t)((lid & 7) + 8 * ((lid >> 3) & 1));
    const uint32_t bq = (uint32_t)((lid & 7) + 8 * (lid >> 4));
    const int mo = lid >> 2;
    const int no = 2 * (lid & 3);

    for (int tile = blockIdx.x; tile < ntiles; tile += gridDim.x) {
        const long long tbase = (long long)tile * 128;

        __syncthreads();

        for (int idx = tid; idx < 54 * 32; idx += FK_TPB) {
            const int k = idx >> 5, s4 = (idx & 31) * 4;
            const float4 f = *(const float4*)(g_p2 + (long long)k * NSMAX + tbase + s4);
            unsigned short h, l;
#pragma unroll
            for (int j = 0; j < 4; j++) {
                const float v = (j == 0) ? f.x : (j == 1) ? f.y : (j == 2) ? f.z : f.w;
                bf16split1(v, h, l);
                *(unsigned short*)(smem + F_P2H + (s4 + j) * 144 + k * 2) = h;
                *(unsigned short*)(smem + F_P2L + (s4 + j) * 144 + k * 2) = l;
            }
        }
        __syncthreads();

        float acc1[2][4][4];
#pragma unroll
        for (int mt = 0; mt < 2; mt++)
#pragma unroll
            for (int nt = 0; nt < 4; nt++)
#pragma unroll
                for (int q = 0; q < 4; q++) acc1[mt][nt][q] = 0.0f;

#pragma unroll
        for (int k0 = 0; k0 < 64; k0 += 16) {
            const uint32_t ac = (uint32_t)(k0 + 8 * (lid >> 4));
            uint32_t ahi[2][4], alo[2][4];
#pragma unroll
            for (int mt = 0; mt < 2; mt++) {
                const uint32_t off = (mbase0 + mt * 16 + ar) * 144 + ac * 2;
                LDSM_X4(ahi[mt][0], ahi[mt][1], ahi[mt][2], ahi[mt][3], sb + F_W1H + off);
                LDSM_X4(alo[mt][0], alo[mt][1], alo[mt][2], alo[mt][3], sb + F_W1L + off);
            }
            const uint32_t bc = (uint32_t)(k0 + 8 * ((lid >> 3) & 1));
#pragma unroll
            for (int np = 0; np < 2; np++) {
                const uint32_t off = (nbase + np * 16 + bq) * 144 + bc * 2;
                uint32_t bh[4], bl[4];
                LDSM_X4(bh[0], bh[1], bh[2], bh[3], sb + F_P2H + off);
                LDSM_X4(bl[0], bl[1], bl[2], bl[3], sb + F_P2L + off);
#pragma unroll
                for (int mt = 0; mt < 2; mt++) {
                    MMA_BF16(acc1[mt][2 * np],     ahi[mt], bh[0], bh[1]);
                    MMA_BF16(acc1[mt][2 * np],     ahi[mt], bl[0], bl[1]);
                    MMA_BF16(acc1[mt][2 * np],     alo[mt], bh[0], bh[1]);
                    MMA_BF16(acc1[mt][2 * np + 1], ahi[mt], bh[2], bh[3]);
                    MMA_BF16(acc1[mt][2 * np + 1], ahi[mt], bl[2], bl[3]);
                    MMA_BF16(acc1[mt][2 * np + 1], alo[mt], bh[2], bh[3]);
                }
            }
        }

        {
            const float* bp = (const float*)(smem + F_B1);
#pragma unroll
            for (int mt = 0; mt < 2; mt++) {
                const int m = mbase0 + mt * 16 + mo;
                const float bA = bp[m], bB = bp[m + 8];
#pragma unroll
                for (int nt = 0; nt < 4; nt++) {
                    const int n = nbase + nt * 8 + no;
                    const float v0 = fmaxf(acc1[mt][nt][0] + bA, 0.0f);
                    const float v1 = fmaxf(acc1[mt][nt][1] + bA, 0.0f);
                    const float v2 = fmaxf(acc1[mt][nt][2] + bB, 0.0f);
                    const float v3 = fmaxf(acc1[mt][nt][3] + bB, 0.0f);
                    unsigned short h, l;
                    bf16split1(v0, h, l);
                    *(unsigned short*)(smem + F_HH + n * 272 + m * 2) = h;
                    *(unsigned short*)(smem + F_HL + n * 272 + m * 2) = l;
                    bf16split1(v1, h, l);
                    *(unsigned short*)(smem + F_HH + (n + 1) * 272 + m * 2) = h;
                    *(unsigned short*)(smem + F_HL + (n + 1) * 272 + m * 2) = l;
                    bf16split1(v2, h, l);
                    *(unsigned short*)(smem + F_HH + n * 272 + (m + 8) * 2) = h;
                    *(unsigned short*)(smem + F_HL + n * 272 + (m + 8) * 2) = l;
                    bf16split1(v3, h, l);
                    *(unsigned short*)(smem + F_HH + (n + 1) * 272 + (m + 8) * 2) = h;
                    *(unsigned short*)(smem + F_HL + (n + 1) * 272 + (m + 8) * 2) = l;
                }
            }
        }
        __syncthreads();

        float acc2[2][4][4];
#pragma unroll
        for (int mt = 0; mt < 2; mt++)
#pragma unroll
            for (int nt = 0; nt < 4; nt++)
#pragma unroll
                for (int q = 0; q < 4; q++) acc2[mt][nt][q] = 0.0f;

#pragma unroll
        for (int k0 = 0; k0 < 128; k0 += 16) {
            const uint32_t ac = (uint32_t)(k0 + 8 * (lid >> 4));
            uint32_t ahi[2][4], alo[2][4];
#pragma unroll
            for (int mt = 0; mt < 2; mt++) {
                const uint32_t off = (mbase0 + mt * 16 + ar) * 272 + ac * 2;
                LDSM_X4(ahi[mt][0], ahi[mt][1], ahi[mt][2], ahi[mt][3], sb + F_W2H + off);
                LDSM_X4(alo[mt][0], alo[mt][1], alo[mt][2], alo[mt][3], sb + F_W2L + off);
            }
            const uint32_t bc = (uint32_t)(k0 + 8 * ((lid >> 3) & 1));
#pragma unroll
            for (int np = 0; np < 2; np++) {
                const uint32_t off = (nbase + np * 16 + bq) * 272 + bc * 2;
                uint32_t bh[4], bl[4];
                LDSM_X4(bh[0], bh[1], bh[2], bh[3], sb + F_HH + off);
                LDSM_X4(bl[0], bl[1], bl[2], bl[3], sb + F_HL + off);
#pragma unroll
                for (int mt = 0; mt < 2; mt++) {
                    MMA_BF16(acc2[mt][2 * np],     ahi[mt], bh[0], bh[1]);
                    MMA_BF16(acc2[mt][2 * np],     ahi[mt], bl[0], bl[1]);
                    MMA_BF16(acc2[mt][2 * np],     alo[mt], bh[0], bh[1]);
                    MMA_BF16(acc2[mt][2 * np + 1], ahi[mt], bh[2], bh[3]);
                    MMA_BF16(acc2[mt][2 * np + 1], ahi[mt], bl[2], bl[3]);
                    MMA_BF16(acc2[mt][2 * np + 1], alo[mt], bh[2], bh[3]);
                }
            }
        }
        __syncthreads();

        {
            float* Dsm = (float*)(smem + F_D);
#pragma unroll
            for (int mt = 0; mt < 2; mt++) {
                const int m = mbase0 + mt * 16 + mo;
#pragma unroll
                for (int nt = 0; nt < 4; nt++) {
                    const int n = nbase + nt * 8 + no;
                    Dsm[n * 132 + m]           = acc2[mt][nt][0];
                    Dsm[(n + 1) * 132 + m]     = acc2[mt][nt][1];
                    Dsm[n * 132 + m + 8]       = acc2[mt][nt][2];
                    Dsm[(n + 1) * 132 + m + 8] = acc2[mt][nt][3];
                }
            }
        }
        __syncthreads();

        {
            const float* Dsm = (const float*)(smem + F_D);
            const float* bp  = (const float*)(smem + F_B2);
            const int s  = tid & 127;
            const int oh = (tid >> 7) * 32;
            const long long gs = tbase + s;
            if (gs < nsamp) {
                float* op = out + gs * 128 + oh;
                const float* dp = Dsm + s * 132 + oh;
#pragma unroll
                for (int i = 0; i < 32; i += 4) {
                    float4 v = *(const float4*)(dp + i);
                    v.x += bp[oh + i];     v.y += bp[oh + i + 1];
                    v.z += bp[oh + i + 2]; v.w += bp[oh + i + 3];
                    *(float4*)(op + i) = v;
                }
            }
        }
    }
}

extern "C" void kernel_launch(void* const* d_in, const int* in_sizes, int n_in,
                              void* d_out, int out_size)
{
    const float* x   = (const float*)d_in[0];
    const float* c1w = (const float*)d_in[1];
    const float* c1b = (const float*)d_in[2];
    const float* c2w = (const float*)d_in[3];
    const float* c2b = (const float*)d_in[4];
    const float* w1  = (const float*)d_in[5];
    const float* b1  = (const float*)d_in[6];
    const float* w2  = (const float*)d_in[7];
    const float* b2  = (const float*)d_in[8];
    float* out = (float*)d_out;

    const int nsamp = in_sizes[0] / 128;

    cudaFuncSetAttribute(convf_kernel, cudaFuncAttributeMaxDynamicSharedMemorySize, CF_SMEM);
    cudaFuncSetAttribute(head_kernel,  cudaFuncAttributeMaxDynamicSharedMemorySize, FK_SMEM);

    convf_kernel<<<(nsamp + CF_TPB - 1) / CF_TPB, CF_TPB, CF_SMEM>>>(x, c1w, c1b, c2w, c2b, nsamp);

    const int ntiles = (nsamp + 127) / 128;
    const int blocks = (ntiles < 148) ? ntiles : 148;
    head_kernel<<<blocks, FK_TPB, FK_SMEM>>>(w1, b1, w2, b2, out, nsamp, ntiles);
}

// round 15
// speedup vs baseline: 1.6282x; 1.6282x over previous
#include <cuda_runtime.h>
#include <cuda_bf16.h>
#include <cstdint>

typedef unsigned long long u64;

#define NSMAX 131072
__device__ float g_c1[108 * NSMAX];   // conv1+pool output [ch*36+y*6+x][sample]
__device__ float g_p2[54 * NSMAX];    // conv2+pool output [k][sample]

__device__ __forceinline__ u64 dup2(float a) {
    u64 r; asm("mov.b64 %0, {%1, %1};" : "=l"(r) : "r"(__float_as_uint(a))); return r;
}
__device__ __forceinline__ u64 pack2(float lo, float hi) {
    u64 r; asm("mov.b64 %0, {%1, %2};" : "=l"(r) : "r"(__float_as_uint(lo)), "r"(__float_as_uint(hi))); return r;
}
__device__ __forceinline__ void fma2(u64& acc, u64 a, u64 b) {
    asm("fma.rn.f32x2 %0, %1, %2, %0;" : "+l"(acc) : "l"(a), "l"(b));
}
__device__ __forceinline__ float2 unpack2(u64 v) {
    unsigned lo, hi; asm("mov.b64 {%0, %1}, %2;" : "=r"(lo), "=r"(hi) : "l"(v));
    return make_float2(__uint_as_float(lo), __uint_as_float(hi));
}

// ================================================================
// Kernel A1: conv1 (1->3, 3x3 pad1, 12x12) + maxpool2 + relu -> g_c1
// 256 thr per-thread; dy-packed f32x2; padded window (no predication)
// ================================================================
#define A1TPB 256
__global__ void __launch_bounds__(A1TPB)
conv1_kernel(const float* __restrict__ x,
             const float* __restrict__ c1w, const float* __restrict__ c1b, int nsamp)
{
    __shared__ float ws[32];
    const int tid = threadIdx.x;
    if (tid < 27) ws[tid] = c1w[tid];
    if (tid < 3)  ws[27 + tid] = c1b[tid];
    __syncthreads();

    const long long s = (long long)blockIdx.x * A1TPB + tid;
    if (s >= nsamp) return;
    const float* xp = x + s * 128;

#pragma unroll
    for (int py = 0; py < 6; py++) {
        // padded rows: r[j][0] and r[j][13] are zero
        float r[4][14];
#pragma unroll
        for (int j = 0; j < 4; j++) {
            const int rr = 2 * py - 1 + j;
            r[j][0] = 0.0f; r[j][13] = 0.0f;
            if (rr < 0 || rr >= 11) {
#pragma unroll
                for (int c = 0; c < 12; c++) r[j][1 + c] = 0.0f;
            } else if (rr == 10) {
#pragma unroll
                for (int c = 0; c < 8; c += 2) {
                    float2 v = *(const float2*)(xp + 120 + c);
                    r[j][1 + c] = v.x; r[j][2 + c] = v.y;
                }
                r[j][9] = 0.0f; r[j][10] = 0.0f; r[j][11] = 0.0f; r[j][12] = 0.0f;
            } else {
#pragma unroll
                for (int c = 0; c < 12; c += 2) {
                    float2 v = *(const float2*)(xp + 12 * rr + c);
                    r[j][1 + c] = v.x; r[j][2 + c] = v.y;
                }
            }
        }
        // pack dy pairs: pr[ky][i] = {r[ky][i] (dy=0), r[ky+1][i] (dy=1)}
        u64 pr[3][14];
#pragma unroll
        for (int j = 0; j < 3; j++)
#pragma unroll
            for (int i = 0; i < 14; i++)
                pr[j][i] = pack2(r[j][i], r[j + 1][i]);

#pragma unroll
        for (int oc = 0; oc < 3; oc++) {
#pragma unroll
            for (int px = 0; px < 6; px++) {
                u64 a0 = 0ull, a1 = 0ull;   // dx=0, dx=1 (lo=dy0, hi=dy1)
#pragma unroll
                for (int ky = 0; ky < 3; ky++) {
#pragma unroll
                    for (int kx = 0; kx < 3; kx++) {
                        const u64 wd = dup2(ws[oc * 9 + ky * 3 + kx]);
                        fma2(a0, wd, pr[ky][2 * px + kx]);       // padded ix0+1
                        fma2(a1, wd, pr[ky][2 * px + kx + 1]);   // padded ix1+1
                    }
                }
                float2 v0 = unpack2(a0), v1 = unpack2(a1);
                float m = fmaxf(fmaxf(v0.x, v0.y), fmaxf(v1.x, v1.y));
                g_c1[(long long)(oc * 36 + py * 6 + px) * NSMAX + s] =
                    fmaxf(m + ws[27 + oc], 0.0f);
            }
        }
    }
}

// ================================================================
// Kernel A2: conv2 (3->6, 3x3 pad1, 6x6) + maxpool2 + relu -> g_p2
// padded pcp[3][8] (no predication in 162-iter inner)
// ================================================================
#define A2TPB 128
__global__ void __launch_bounds__(A2TPB)
conv2_kernel(const float* __restrict__ c2w, const float* __restrict__ c2b, int nsamp)
{
    __shared__ float ws[168];
    const int tid = threadIdx.x;
    for (int i = tid; i < 162; i += A2TPB) ws[i] = c2w[i];
    for (int i = tid; i < 6;   i += A2TPB) ws[162 + i] = c2b[i];
    __syncthreads();

    const long long s = (long long)blockIdx.x * A2TPB + tid;
    if (s >= nsamp) return;

#pragma unroll
    for (int py = 0; py < 3; py++) {
        u64 acc[6][3][2];
#pragma unroll
        for (int oc = 0; oc < 6; oc++)
#pragma unroll
            for (int px = 0; px < 3; px++) { acc[oc][px][0] = 0ull; acc[oc][px][1] = 0ull; }

#pragma unroll
        for (int ic = 0; ic < 3; ic++) {
            float rw[4][6];
#pragma unroll
            for (int j = 0; j < 4; j++) {
                const int y = 2 * py - 1 + j;
                if (y < 0 || y > 5) {
#pragma unroll
                    for (int ix = 0; ix < 6; ix++) rw[j][ix] = 0.0f;
                } else {
#pragma unroll
                    for (int ix = 0; ix < 6; ix++)
                        rw[j][ix] = g_c1[(long long)(ic * 36 + y * 6 + ix) * NSMAX + s];
                }
            }
            u64 pcp[3][8];          // padded: index 0 and 7 are zero
#pragma unroll
            for (int j = 0; j < 3; j++) {
                pcp[j][0] = 0ull; pcp[j][7] = 0ull;
#pragma unroll
                for (int ix = 0; ix < 6; ix++)
                    pcp[j][1 + ix] = pack2(rw[j][ix], rw[j + 1][ix]);
            }

#pragma unroll
            for (int oc = 0; oc < 6; oc++) {
#pragma unroll
                for (int ky = 0; ky < 3; ky++) {
#pragma unroll
                    for (int kx = 0; kx < 3; kx++) {
                        const u64 wd = dup2(ws[oc * 27 + ic * 9 + ky * 3 + kx]);
#pragma unroll
                        for (int px = 0; px < 3; px++) {
                            fma2(acc[oc][px][0], wd, pcp[ky][2 * px + kx]);
                            fma2(acc[oc][px][1], wd, pcp[ky][2 * px + kx + 1]);
                        }
                    }
                }
            }
        }
#pragma unroll
        for (int oc = 0; oc < 6; oc++) {
            const float bb = ws[162 + oc];
#pragma unroll
            for (int px = 0; px < 3; px++) {
                float2 v0 = unpack2(acc[oc][px][0]), v1 = unpack2(acc[oc][px][1]);
                float m = fmaxf(fmaxf(v0.x, v0.y), fmaxf(v1.x, v1.y));
                g_p2[(long long)(oc * 9 + py * 3 + px) * NSMAX + s] = fmaxf(m + bb, 0.0f);
            }
        }
    }
}

// ================================================================
// Kernel F: fused fc1+relu+out, chained mma.sync bf16 3-term split
// 512 threads; warp grid 4(m) x 4(n); warp tile m32 x n32  (round-11 proven)
// ================================================================
#define FK_TPB  512
#define F_B1   0
#define F_B2   512
#define F_W1H  1024
#define F_W1L  19456
#define F_W2H  37888
#define F_W2L  72704
#define F_P2H  107520
#define F_P2L  125952
#define F_HH   144384
#define F_HL   179200
#define F_D    144384
#define FK_SMEM 214016

#define LDSM_X4(r0, r1, r2, r3, addr) \
    asm volatile("ldmatrix.sync.aligned.m8n8.x4.shared.b16 {%0,%1,%2,%3}, [%4];" \
        : "=r"(r0), "=r"(r1), "=r"(r2), "=r"(r3) : "r"(addr))

#define MMA_BF16(c, a, b0, b1) \
    asm volatile("mma.sync.aligned.m16n8k16.row.col.f32.bf16.bf16.f32 " \
        "{%0,%1,%2,%3}, {%4,%5,%6,%7}, {%8,%9}, {%0,%1,%2,%3};" \
        : "+f"((c)[0]), "+f"((c)[1]), "+f"((c)[2]), "+f"((c)[3]) \
        : "r"((a)[0]), "r"((a)[1]), "r"((a)[2]), "r"((a)[3]), "r"(b0), "r"(b1))

__device__ __forceinline__ uint32_t smem_u32(const void* p) {
    uint32_t a;
    asm("{ .reg .u64 t; cvta.to.shared.u64 t, %1; cvt.u32.u64 %0, t; }" : "=r"(a) : "l"(p));
    return a;
}
__device__ __forceinline__ void bf16split(float f0, float f1, unsigned& hi, unsigned& lo) {
    asm("cvt.rn.bf16x2.f32 %0, %1, %2;" : "=r"(hi) : "f"(f1), "f"(f0));
    const float h0 = __uint_as_float(hi << 16);
    const float h1 = __uint_as_float(hi & 0xFFFF0000u);
    const float r0 = f0 - h0, r1 = f1 - h1;
    asm("cvt.rn.bf16x2.f32 %0, %1, %2;" : "=r"(lo) : "f"(r1), "f"(r0));
}
__device__ __forceinline__ void bf16split1(float v, unsigned short& hi, unsigned short& lo) {
    __nv_bfloat16 h = __float2bfloat16(v);
    float r = v - __bfloat162float(h);
    __nv_bfloat16 l = __float2bfloat16(r);
    hi = *(unsigned short*)&h;
    lo = *(unsigned short*)&l;
}

__global__ void __launch_bounds__(FK_TPB, 1)
head_kernel(const float* __restrict__ w1, const float* __restrict__ b1,
            const float* __restrict__ w2, const float* __restrict__ b2,
            float* __restrict__ out, int nsamp, int ntiles)
{
    extern __shared__ char smem[];
    const uint32_t sb = smem_u32(smem);
    const int tid = threadIdx.x;
    const int wid = tid >> 5, lid = tid & 31;

    if (tid < 128) { ((float*)(smem + F_B1))[tid] = b1[tid];
                     ((float*)(smem + F_B2))[tid] = b2[tid]; }
    for (int i = tid; i < 9216; i += FK_TPB) {
        ((uint32_t*)(smem + F_W1H))[i] = 0u;      // zero W1H+W1L (contiguous)
        ((uint32_t*)(smem + F_P2H))[i] = 0u;      // zero P2H+P2L (contiguous)
    }
    __syncthreads();
    if (tid < 128) {
        const int o = tid;
        const float* wr = w1 + o * 54;
        char* ah = smem + F_W1H + o * 144;
        char* al = smem + F_W1L + o * 144;
        for (int i = 0; i < 54; i += 2) {
            const float2 f = *(const float2*)(wr + i);
            unsigned h, l;
            bf16split(f.x, f.y, h, l);
            *(unsigned*)(ah + i * 2) = h;
            *(unsigned*)(al + i * 2) = l;
        }
    }
    {
        const int o  = tid & 127;
        const int kq = (tid >> 7) * 32;
        const float* wr = w2 + o * 128 + kq;
        char* ah = smem + F_W2H + o * 272 + kq * 2;
        char* al = smem + F_W2L + o * 272 + kq * 2;
        for (int i = 0; i < 32; i += 4) {
            const float4 f = *(const float4*)(wr + i);
            unsigned h0, l0, h1, l1;
            bf16split(f.x, f.y, h0, l0);
            bf16split(f.z, f.w, h1, l1);
            *(uint2*)(ah + i * 2) = make_uint2(h0, h1);
            *(uint2*)(al + i * 2) = make_uint2(l0, l1);
        }
    }

    const int mgrp = wid & 3;
    const int ngrp = wid >> 2;
    const int mbase0 = mgrp * 32;
    const int nbase  = ngrp * 32;
    const uint32_t ar = (uint32_t)((lid & 7) + 8 * ((lid >> 3) & 1));
    const uint32_t bq = (uint32_t)((lid & 7) + 8 * (lid >> 4));
    const int mo = lid >> 2;
    const int no = 2 * (lid & 3);

    for (int tile = blockIdx.x; tile < ntiles; tile += gridDim.x) {
        const long long tbase = (long long)tile * 128;

        __syncthreads();

        for (int idx = tid; idx < 54 * 32; idx += FK_TPB) {
            const int k = idx >> 5, s4 = (idx & 31) * 4;
            const float4 f = *(const float4*)(g_p2 + (long long)k * NSMAX + tbase + s4);
            unsigned short h, l;
#pragma unroll
            for (int j = 0; j < 4; j++) {
                const float v = (j == 0) ? f.x : (j == 1) ? f.y : (j == 2) ? f.z : f.w;
                bf16split1(v, h, l);
                *(unsigned short*)(smem + F_P2H + (s4 + j) * 144 + k * 2) = h;
                *(unsigned short*)(smem + F_P2L + (s4 + j) * 144 + k * 2) = l;
            }
        }
        __syncthreads();

        float acc1[2][4][4];
#pragma unroll
        for (int mt = 0; mt < 2; mt++)
#pragma unroll
            for (int nt = 0; nt < 4; nt++)
#pragma unroll
                for (int q = 0; q < 4; q++) acc1[mt][nt][q] = 0.0f;

#pragma unroll
        for (int k0 = 0; k0 < 64; k0 += 16) {
            const uint32_t ac = (uint32_t)(k0 + 8 * (lid >> 4));
            uint32_t ahi[2][4], alo[2][4];
#pragma unroll
            for (int mt = 0; mt < 2; mt++) {
                const uint32_t off = (mbase0 + mt * 16 + ar) * 144 + ac * 2;
                LDSM_X4(ahi[mt][0], ahi[mt][1], ahi[mt][2], ahi[mt][3], sb + F_W1H + off);
                LDSM_X4(alo[mt][0], alo[mt][1], alo[mt][2], alo[mt][3], sb + F_W1L + off);
            }
            const uint32_t bc = (uint32_t)(k0 + 8 * ((lid >> 3) & 1));
#pragma unroll
            for (int np = 0; np < 2; np++) {
                const uint32_t off = (nbase + np * 16 + bq) * 144 + bc * 2;
                uint32_t bh[4], bl[4];
                LDSM_X4(bh[0], bh[1], bh[2], bh[3], sb + F_P2H + off);
                LDSM_X4(bl[0], bl[1], bl[2], bl[3], sb + F_P2L + off);
#pragma unroll
                for (int mt = 0; mt < 2; mt++) {
                    MMA_BF16(acc1[mt][2 * np],     ahi[mt], bh[0], bh[1]);
                    MMA_BF16(acc1[mt][2 * np],     ahi[mt], bl[0], bl[1]);
                    MMA_BF16(acc1[mt][2 * np],     alo[mt], bh[0], bh[1]);
                    MMA_BF16(acc1[mt][2 * np + 1], ahi[mt], bh[2], bh[3]);
                    MMA_BF16(acc1[mt][2 * np + 1], ahi[mt], bl[2], bl[3]);
                    MMA_BF16(acc1[mt][2 * np + 1], alo[mt], bh[2], bh[3]);
                }
            }
        }

        {
            const float* bp = (const float*)(smem + F_B1);
#pragma unroll
            for (int mt = 0; mt < 2; mt++) {
                const int m = mbase0 + mt * 16 + mo;
                const float bA = bp[m], bB = bp[m + 8];
#pragma unroll
                for (int nt = 0; nt < 4; nt++) {
                    const int n = nbase + nt * 8 + no;
                    const float v0 = fmaxf(acc1[mt][nt][0] + bA, 0.0f);
                    const float v1 = fmaxf(acc1[mt][nt][1] + bA, 0.0f);
                    const float v2 = fmaxf(acc1[mt][nt][2] + bB, 0.0f);
                    const float v3 = fmaxf(acc1[mt][nt][3] + bB, 0.0f);
                    unsigned short h, l;
                    bf16split1(v0, h, l);
                    *(unsigned short*)(smem + F_HH + n * 272 + m * 2) = h;
                    *(unsigned short*)(smem + F_HL + n * 272 + m * 2) = l;
                    bf16split1(v1, h, l);
                    *(unsigned short*)(smem + F_HH + (n + 1) * 272 + m * 2) = h;
                    *(unsigned short*)(smem + F_HL + (n + 1) * 272 + m * 2) = l;
                    bf16split1(v2, h, l);
                    *(unsigned short*)(smem + F_HH + n * 272 + (m + 8) * 2) = h;
                    *(unsigned short*)(smem + F_HL + n * 272 + (m + 8) * 2) = l;
                    bf16split1(v3, h, l);
                    *(unsigned short*)(smem + F_HH + (n + 1) * 272 + (m + 8) * 2) = h;
                    *(unsigned short*)(smem + F_HL + (n + 1) * 272 + (m + 8) * 2) = l;
                }
            }
        }
        __syncthreads();

        float acc2[2][4][4];
#pragma unroll
        for (int mt = 0; mt < 2; mt++)
#pragma unroll
            for (int nt = 0; nt < 4; nt++)
#pragma unroll
                for (int q = 0; q < 4; q++) acc2[mt][nt][q] = 0.0f;

#pragma unroll
        for (int k0 = 0; k0 < 128; k0 += 16) {
            const uint32_t ac = (uint32_t)(k0 + 8 * (lid >> 4));
            uint32_t ahi[2][4], alo[2][4];
#pragma unroll
            for (int mt = 0; mt < 2; mt++) {
                const uint32_t off = (mbase0 + mt * 16 + ar) * 272 + ac * 2;
                LDSM_X4(ahi[mt][0], ahi[mt][1], ahi[mt][2], ahi[mt][3], sb + F_W2H + off);
                LDSM_X4(alo[mt][0], alo[mt][1], alo[mt][2], alo[mt][3], sb + F_W2L + off);
            }
            const uint32_t bc = (uint32_t)(k0 + 8 * ((lid >> 3) & 1));
#pragma unroll
            for (int np = 0; np < 2; np++) {
                const uint32_t off = (nbase + np * 16 + bq) * 272 + bc * 2;
                uint32_t bh[4], bl[4];
                LDSM_X4(bh[0], bh[1], bh[2], bh[3], sb + F_HH + off);
                LDSM_X4(bl[0], bl[1], bl[2], bl[3], sb + F_HL + off);
#pragma unroll
                for (int mt = 0; mt < 2; mt++) {
                    MMA_BF16(acc2[mt][2 * np],     ahi[mt], bh[0], bh[1]);
                    MMA_BF16(acc2[mt][2 * np],     ahi[mt], bl[0], bl[1]);
                    MMA_BF16(acc2[mt][2 * np],     alo[mt], bh[0], bh[1]);
                    MMA_BF16(acc2[mt][2 * np + 1], ahi[mt], bh[2], bh[3]);
                    MMA_BF16(acc2[mt][2 * np + 1], ahi[mt], bl[2], bl[3]);
                    MMA_BF16(acc2[mt][2 * np + 1], alo[mt], bh[2], bh[3]);
                }
            }
        }
        __syncthreads();

        {
            float* Dsm = (float*)(smem + F_D);
#pragma unroll
            for (int mt = 0; mt < 2; mt++) {
                const int m = mbase0 + mt * 16 + mo;
#pragma unroll
                for (int nt = 0; nt < 4; nt++) {
                    const int n = nbase + nt * 8 + no;
                    Dsm[n * 132 + m]           = acc2[mt][nt][0];
                    Dsm[(n + 1) * 132 + m]     = acc2[mt][nt][1];
                    Dsm[n * 132 + m + 8]       = acc2[mt][nt][2];
                    Dsm[(n + 1) * 132 + m + 8] = acc2[mt][nt][3];
                }
            }
        }
        __syncthreads();

        {
            const float* Dsm = (const float*)(smem + F_D);
            const float* bp  = (const float*)(smem + F_B2);
            const int s  = tid & 127;
            const int oh = (tid >> 7) * 32;
            const long long gs = tbase + s;
            if (gs < nsamp) {
                float* op = out + gs * 128 + oh;
                const float* dp = Dsm + s * 132 + oh;
#pragma unroll
                for (int i = 0; i < 32; i += 4) {
                    float4 v = *(const float4*)(dp + i);
                    v.x += bp[oh + i];     v.y += bp[oh + i + 1];
                    v.z += bp[oh + i + 2]; v.w += bp[oh + i + 3];
                    *(float4*)(op + i) = v;
                }
            }
        }
    }
}

extern "C" void kernel_launch(void* const* d_in, const int* in_sizes, int n_in,
                              void* d_out, int out_size)
{
    const float* x   = (const float*)d_in[0];
    const float* c1w = (const float*)d_in[1];
    const float* c1b = (const float*)d_in[2];
    const float* c2w = (const float*)d_in[3];
    const float* c2b = (const float*)d_in[4];
    const float* w1  = (const float*)d_in[5];
    const float* b1  = (const float*)d_in[6];
    const float* w2  = (const float*)d_in[7];
    const float* b2  = (const float*)d_in[8];
    float* out = (float*)d_out;

    const int nsamp = in_sizes[0] / 128;

    cudaFuncSetAttribute(head_kernel, cudaFuncAttributeMaxDynamicSharedMemorySize, FK_SMEM);

    conv1_kernel<<<(nsamp + A1TPB - 1) / A1TPB, A1TPB>>>(x, c1w, c1b, nsamp);
    conv2_kernel<<<(nsamp + A2TPB - 1) / A2TPB, A2TPB>>>(c2w, c2b, nsamp);

    const int ntiles = (nsamp + 127) / 128;
    const int blocks = (ntiles < 148) ? ntiles : 148;
    head_kernel<<<blocks, FK_TPB, FK_SMEM>>>(w1, b1, w2, b2, out, nsamp, ntiles);
}

// round 16
// speedup vs baseline: 1.6596x; 1.0193x over previous
#include <cuda_runtime.h>
#include <cuda_bf16.h>
#include <cstdint>

typedef unsigned long long u64;

#define NSMAX 131072
__device__ float g_c1[108 * NSMAX];   // conv1+pool output [ch*36+y*6+x][sample]
__device__ float g_p2[54 * NSMAX];    // conv2+pool output [k][sample]

__device__ __forceinline__ u64 dup2(float a) {
    u64 r; asm("mov.b64 %0, {%1, %1};" : "=l"(r) : "r"(__float_as_uint(a))); return r;
}
__device__ __forceinline__ u64 pack2(float lo, float hi) {
    u64 r; asm("mov.b64 %0, {%1, %2};" : "=l"(r) : "r"(__float_as_uint(lo)), "r"(__float_as_uint(hi))); return r;
}
__device__ __forceinline__ void fma2(u64& acc, u64 a, u64 b) {
    asm("fma.rn.f32x2 %0, %1, %2, %0;" : "+l"(acc) : "l"(a), "l"(b));
}
__device__ __forceinline__ float2 unpack2(u64 v) {
    unsigned lo, hi; asm("mov.b64 {%0, %1}, %2;" : "=r"(lo), "=r"(hi) : "l"(v));
    return make_float2(__uint_as_float(lo), __uint_as_float(hi));
}

// ================================================================
// Kernel A1: conv1 (1->3, 3x3 pad1, 12x12) + maxpool2 + relu -> g_c1
// 256 thr / 128 samples (2 threads per sample: py halves); x staged in smem
// ================================================================
#define A1TPB 256
#define A1_XS 129
#define A1_SMEM (128 * A1_XS * 4)

template<int PY>
__device__ __forceinline__ void conv1_py(const float* __restrict__ xp,
                                         const float* __restrict__ W,
                                         float B0, float B1, float B2,
                                         long long s)
{
    float r[4][14];            // padded: index 0 and 13 are zero
#pragma unroll
    for (int j = 0; j < 4; j++) {
        const int rr = 2 * PY - 1 + j;
        r[j][0] = 0.0f; r[j][13] = 0.0f;
        if (rr < 0 || rr >= 11) {
#pragma unroll
            for (int c = 0; c < 12; c++) r[j][1 + c] = 0.0f;
        } else if (rr == 10) {
#pragma unroll
            for (int c = 0; c < 8; c++) r[j][1 + c] = xp[120 + c];
            r[j][9] = 0.0f; r[j][10] = 0.0f; r[j][11] = 0.0f; r[j][12] = 0.0f;
        } else {
#pragma unroll
            for (int c = 0; c < 12; c++) r[j][1 + c] = xp[12 * rr + c];
        }
    }
#pragma unroll
    for (int oc = 0; oc < 3; oc++) {
        float v0[12], v1[12];
#pragma unroll
        for (int cx = 0; cx < 12; cx++) {
            float a0 = 0.0f, a1 = 0.0f;
#pragma unroll
            for (int ky = 0; ky < 3; ky++) {
#pragma unroll
                for (int kx = 0; kx < 3; kx++) {
                    const float w = W[oc * 9 + ky * 3 + kx];
                    a0 = fmaf(w, r[ky][cx + kx],     a0);
                    a1 = fmaf(w, r[ky + 1][cx + kx], a1);
                }
            }
            v0[cx] = a0; v1[cx] = a1;
        }
        const float bb = (oc == 0) ? B0 : ((oc == 1) ? B1 : B2);
#pragma unroll
        for (int px = 0; px < 6; px++) {
            float m = fmaxf(fmaxf(v0[2 * px], v0[2 * px + 1]),
                            fmaxf(v1[2 * px], v1[2 * px + 1]));
            g_c1[(long long)(oc * 36 + PY * 6 + px) * NSMAX + s] = fmaxf(m + bb, 0.0f);
        }
    }
}

__global__ void __launch_bounds__(A1TPB, 3)
conv1_kernel(const float* __restrict__ x,
             const float* __restrict__ c1w, const float* __restrict__ c1b, int nsamp)
{
    extern __shared__ float sx[];
    __shared__ float ws[32];
    const int tid = threadIdx.x;
    if (tid < 27) ws[tid] = c1w[tid];
    if (tid < 3)  ws[27 + tid] = c1b[tid];

    const long long base = (long long)blockIdx.x * 128;

    // coalesced stage of 128-sample x tile into smem (stride 129)
    for (int i = tid; i < 128 * 32; i += A1TPB) {
        const int row = i >> 5, q = (i & 31) * 4;
        const long long s = base + row;
        float4 v = make_float4(0.f, 0.f, 0.f, 0.f);
        if (s < nsamp) v = *(const float4*)(x + s * 128 + q);
        float* d = sx + row * A1_XS + q;
        d[0] = v.x; d[1] = v.y; d[2] = v.z; d[3] = v.w;
    }
    __syncthreads();

    const int sid  = tid & 127;
    const int half = tid >> 7;
    const long long s = base + sid;
    if (s >= nsamp) return;
    const float* xp = sx + sid * A1_XS;

    float W[27];
#pragma unroll
    for (int i = 0; i < 27; i++) W[i] = ws[i];
    const float B0 = ws[27], B1 = ws[28], B2 = ws[29];

    if (half == 0) {
        conv1_py<0>(xp, W, B0, B1, B2, s);
        conv1_py<1>(xp, W, B0, B1, B2, s);
        conv1_py<2>(xp, W, B0, B1, B2, s);
    } else {
        conv1_py<3>(xp, W, B0, B1, B2, s);
        conv1_py<4>(xp, W, B0, B1, B2, s);
        conv1_py<5>(xp, W, B0, B1, B2, s);
    }
}

// ================================================================
// Kernel A2: conv2 (3->6, 3x3 pad1, 6x6) + maxpool2 + relu -> g_p2
// 384 thr / 128 samples (3 threads per sample: one py band each)
// ================================================================
#define A2TPB 384

template<int PY>
__device__ __forceinline__ void conv2_band(const float* __restrict__ ws, long long s)
{
    u64 acc[6][3][2];
#pragma unroll
    for (int oc = 0; oc < 6; oc++)
#pragma unroll
        for (int px = 0; px < 3; px++) { acc[oc][px][0] = 0ull; acc[oc][px][1] = 0ull; }

#pragma unroll
    for (int ic = 0; ic < 3; ic++) {
        float rw[4][6];
#pragma unroll
        for (int j = 0; j < 4; j++) {
            const int y = 2 * PY - 1 + j;
            if (y < 0 || y > 5) {
#pragma unroll
                for (int ix = 0; ix < 6; ix++) rw[j][ix] = 0.0f;
            } else {
#pragma unroll
                for (int ix = 0; ix < 6; ix++)
                    rw[j][ix] = g_c1[(long long)(ic * 36 + y * 6 + ix) * NSMAX + s];
            }
        }
        u64 pcp[3][8];          // padded: index 0 and 7 are zero
#pragma unroll
        for (int j = 0; j < 3; j++) {
            pcp[j][0] = 0ull; pcp[j][7] = 0ull;
#pragma unroll
            for (int ix = 0; ix < 6; ix++)
                pcp[j][1 + ix] = pack2(rw[j][ix], rw[j + 1][ix]);
        }

#pragma unroll
        for (int oc = 0; oc < 6; oc++) {
#pragma unroll
            for (int ky = 0; ky < 3; ky++) {
#pragma unroll
                for (int kx = 0; kx < 3; kx++) {
                    const u64 wd = dup2(ws[oc * 27 + ic * 9 + ky * 3 + kx]);
#pragma unroll
                    for (int px = 0; px < 3; px++) {
                        fma2(acc[oc][px][0], wd, pcp[ky][2 * px + kx]);
                        fma2(acc[oc][px][1], wd, pcp[ky][2 * px + kx + 1]);
                    }
                }
            }
        }
    }
#pragma unroll
    for (int oc = 0; oc < 6; oc++) {
        const float bb = ws[162 + oc];
#pragma unroll
        for (int px = 0; px < 3; px++) {
            float2 v0 = unpack2(acc[oc][px][0]), v1 = unpack2(acc[oc][px][1]);
            float m = fmaxf(fmaxf(v0.x, v0.y), fmaxf(v1.x, v1.y));
            g_p2[(long long)(oc * 9 + PY * 3 + px) * NSMAX + s] = fmaxf(m + bb, 0.0f);
        }
    }
}

__global__ void __launch_bounds__(A2TPB)
conv2_kernel(const float* __restrict__ c2w, const float* __restrict__ c2b, int nsamp)
{
    __shared__ float ws[168];
    const int tid = threadIdx.x;
    for (int i = tid; i < 162; i += A2TPB) ws[i] = c2w[i];
    for (int i = tid; i < 6;   i += A2TPB) ws[162 + i] = c2b[i];
    __syncthreads();

    const int sid  = tid & 127;
    const int band = tid >> 7;          // 0,1,2
    const long long s = (long long)blockIdx.x * 128 + sid;
    if (s >= nsamp) return;

    if (band == 0)      conv2_band<0>(ws, s);
    else if (band == 1) conv2_band<1>(ws, s);
    else                conv2_band<2>(ws, s);
}

// ================================================================
// Kernel F: fused fc1+relu+out, chained mma.sync bf16 3-term split
// 512 threads; warp grid 4(m) x 4(n); warp tile m32 x n32  (round-11 proven)
// ================================================================
#define FK_TPB  512
#define F_B1   0
#define F_B2   512
#define F_W1H  1024
#define F_W1L  19456
#define F_W2H  37888
#define F_W2L  72704
#define F_P2H  107520
#define F_P2L  125952
#define F_HH   144384
#define F_HL   179200
#define F_D    144384
#define FK_SMEM 214016

#define LDSM_X4(r0, r1, r2, r3, addr) \
    asm volatile("ldmatrix.sync.aligned.m8n8.x4.shared.b16 {%0,%1,%2,%3}, [%4];" \
        : "=r"(r0), "=r"(r1), "=r"(r2), "=r"(r3) : "r"(addr))

#define MMA_BF16(c, a, b0, b1) \
    asm volatile("mma.sync.aligned.m16n8k16.row.col.f32.bf16.bf16.f32 " \
        "{%0,%1,%2,%3}, {%4,%5,%6,%7}, {%8,%9}, {%0,%1,%2,%3};" \
        : "+f"((c)[0]), "+f"((c)[1]), "+f"((c)[2]), "+f"((c)[3]) \
        : "r"((a)[0]), "r"((a)[1]), "r"((a)[2]), "r"((a)[3]), "r"(b0), "r"(b1))

__device__ __forceinline__ uint32_t smem_u32(const void* p) {
    uint32_t a;
    asm("{ .reg .u64 t; cvta.to.shared.u64 t, %1; cvt.u32.u64 %0, t; }" : "=r"(a) : "l"(p));
    return a;
}
__device__ __forceinline__ void bf16split(float f0, float f1, unsigned& hi, unsigned& lo) {
    asm("cvt.rn.bf16x2.f32 %0, %1, %2;" : "=r"(hi) : "f"(f1), "f"(f0));
    const float h0 = __uint_as_float(hi << 16);
    const float h1 = __uint_as_float(hi & 0xFFFF0000u);
    const float r0 = f0 - h0, r1 = f1 - h1;
    asm("cvt.rn.bf16x2.f32 %0, %1, %2;" : "=r"(lo) : "f"(r1), "f"(r0));
}
__device__ __forceinline__ void bf16split1(float v, unsigned short& hi, unsigned short& lo) {
    __nv_bfloat16 h = __float2bfloat16(v);
    float r = v - __bfloat162float(h);
    __nv_bfloat16 l = __float2bfloat16(r);
    hi = *(unsigned short*)&h;
    lo = *(unsigned short*)&l;
}

__global__ void __launch_bounds__(FK_TPB, 1)
head_kernel(const float* __restrict__ w1, const float* __restrict__ b1,
            const float* __restrict__ w2, const float* __restrict__ b2,
            float* __restrict__ out, int nsamp, int ntiles)
{
    extern __shared__ char smem[];
    const uint32_t sb = smem_u32(smem);
    const int tid = threadIdx.x;
    const int wid = tid >> 5, lid = tid & 31;

    if (tid < 128) { ((float*)(smem + F_B1))[tid] = b1[tid];
                     ((float*)(smem + F_B2))[tid] = b2[tid]; }
    for (int i = tid; i < 9216; i += FK_TPB) {
        ((uint32_t*)(smem + F_W1H))[i] = 0u;      // zero W1H+W1L (contiguous)
        ((uint32_t*)(smem + F_P2H))[i] = 0u;      // zero P2H+P2L (contiguous)
    }
    __syncthreads();
    if (tid < 128) {
        const int o = tid;
        const float* wr = w1 + o * 54;
        char* ah = smem + F_W1H + o * 144;
        char* al = smem + F_W1L + o * 144;
        for (int i = 0; i < 54; i += 2) {
            const float2 f = *(const float2*)(wr + i);
            unsigned h, l;
            bf16split(f.x, f.y, h, l);
            *(unsigned*)(ah + i * 2) = h;
            *(unsigned*)(al + i * 2) = l;
        }
    }
    {
        const int o  = tid & 127;
        const int kq = (tid >> 7) * 32;
        const float* wr = w2 + o * 128 + kq;
        char* ah = smem + F_W2H + o * 272 + kq * 2;
        char* al = smem + F_W2L + o * 272 + kq * 2;
        for (int i = 0; i < 32; i += 4) {
            const float4 f = *(const float4*)(wr + i);
            unsigned h0, l0, h1, l1;
            bf16split(f.x, f.y, h0, l0);
            bf16split(f.z, f.w, h1, l1);
            *(uint2*)(ah + i * 2) = make_uint2(h0, h1);
            *(uint2*)(al + i * 2) = make_uint2(l0, l1);
        }
    }

    const int mgrp = wid & 3;
    const int ngrp = wid >> 2;
    const int mbase0 = mgrp * 32;
    const int nbase  = ngrp * 32;
    const uint32_t ar = (uint32_t)((lid & 7) + 8 * ((lid >> 3) & 1));
    const uint32_t bq = (uint32_t)((lid & 7) + 8 * (lid >> 4));
    const int mo = lid >> 2;
    const int no = 2 * (lid & 3);

    for (int tile = blockIdx.x; tile < ntiles; tile += gridDim.x) {
        const long long tbase = (long long)tile * 128;

        __syncthreads();

        for (int idx = tid; idx < 54 * 32; idx += FK_TPB) {
            const int k = idx >> 5, s4 = (idx & 31) * 4;
            const float4 f = *(const float4*)(g_p2 + (long long)k * NSMAX + tbase + s4);
            unsigned short h, l;
#pragma unroll
            for (int j = 0; j < 4; j++) {
                const float v = (j == 0) ? f.x : (j == 1) ? f.y : (j == 2) ? f.z : f.w;
                bf16split1(v, h, l);
                *(unsigned short*)(smem + F_P2H + (s4 + j) * 144 + k * 2) = h;
                *(unsigned short*)(smem + F_P2L + (s4 + j) * 144 + k * 2) = l;
            }
        }
        __syncthreads();

        float acc1[2][4][4];
#pragma unroll
        for (int mt = 0; mt < 2; mt++)
#pragma unroll
            for (int nt = 0; nt < 4; nt++)
#pragma unroll
                for (int q = 0; q < 4; q++) acc1[mt][nt][q] = 0.0f;

#pragma unroll
        for (int k0 = 0; k0 < 64; k0 += 16) {
            const uint32_t ac = (uint32_t)(k0 + 8 * (lid >> 4));
            uint32_t ahi[2][4], alo[2][4];
#pragma unroll
            for (int mt = 0; mt < 2; mt++) {
                const uint32_t off = (mbase0 + mt * 16 + ar) * 144 + ac * 2;
                LDSM_X4(ahi[mt][0], ahi[mt][1], ahi[mt][2], ahi[mt][3], sb + F_W1H + off);
                LDSM_X4(alo[mt][0], alo[mt][1], alo[mt][2], alo[mt][3], sb + F_W1L + off);
            }
            const uint32_t bc = (uint32_t)(k0 + 8 * ((lid >> 3) & 1));
#pragma unroll
            for (int np = 0; np < 2; np++) {
                const uint32_t off = (nbase + np * 16 + bq) * 144 + bc * 2;
                uint32_t bh[4], bl[4];
                LDSM_X4(bh[0], bh[1], bh[2], bh[3], sb + F_P2H + off);
                LDSM_X4(bl[0], bl[1], bl[2], bl[3], sb + F_P2L + off);
#pragma unroll
                for (int mt = 0; mt < 2; mt++) {
                    MMA_BF16(acc1[mt][2 * np],     ahi[mt], bh[0], bh[1]);
                    MMA_BF16(acc1[mt][2 * np],     ahi[mt], bl[0], bl[1]);
                    MMA_BF16(acc1[mt][2 * np],     alo[mt], bh[0], bh[1]);
                    MMA_BF16(acc1[mt][2 * np + 1], ahi[mt], bh[2], bh[3]);
                    MMA_BF16(acc1[mt][2 * np + 1], ahi[mt], bl[2], bl[3]);
                    MMA_BF16(acc1[mt][2 * np + 1], alo[mt], bh[2], bh[3]);
                }
            }
        }

        {
            const float* bp = (const float*)(smem + F_B1);
#pragma unroll
            for (int mt = 0; mt < 2; mt++) {
                const int m = mbase0 + mt * 16 + mo;
                const float bA = bp[m], bB = bp[m + 8];
#pragma unroll
                for (int nt = 0; nt < 4; nt++) {
                    const int n = nbase + nt * 8 + no;
                    const float v0 = fmaxf(acc1[mt][nt][0] + bA, 0.0f);
                    const float v1 = fmaxf(acc1[mt][nt][1] + bA, 0.0f);
                    const float v2 = fmaxf(acc1[mt][nt][2] + bB, 0.0f);
                    const float v3 = fmaxf(acc1[mt][nt][3] + bB, 0.0f);
                    unsigned short h, l;
                    bf16split1(v0, h, l);
                    *(unsigned short*)(smem + F_HH + n * 272 + m * 2) = h;
                    *(unsigned short*)(smem + F_HL + n * 272 + m * 2) = l;
                    bf16split1(v1, h, l);
                    *(unsigned short*)(smem + F_HH + (n + 1) * 272 + m * 2) = h;
                    *(unsigned short*)(smem + F_HL + (n + 1) * 272 + m * 2) = l;
                    bf16split1(v2, h, l);
                    *(unsigned short*)(smem + F_HH + n * 272 + (m + 8) * 2) = h;
                    *(unsigned short*)(smem + F_HL + n * 272 + (m + 8) * 2) = l;
                    bf16split1(v3, h, l);
                    *(unsigned short*)(smem + F_HH + (n + 1) * 272 + (m + 8) * 2) = h;
                    *(unsigned short*)(smem + F_HL + (n + 1) * 272 + (m + 8) * 2) = l;
                }
            }
        }
        __syncthreads();

        float acc2[2][4][4];
#pragma unroll
        for (int mt = 0; mt < 2; mt++)
#pragma unroll
            for (int nt = 0; nt < 4; nt++)
#pragma unroll
                for (int q = 0; q < 4; q++) acc2[mt][nt][q] = 0.0f;

#pragma unroll
        for (int k0 = 0; k0 < 128; k0 += 16) {
            const uint32_t ac = (uint32_t)(k0 + 8 * (lid >> 4));
            uint32_t ahi[2][4], alo[2][4];
#pragma unroll
            for (int mt = 0; mt < 2; mt++) {
                const uint32_t off = (mbase0 + mt * 16 + ar) * 272 + ac * 2;
                LDSM_X4(ahi[mt][0], ahi[mt][1], ahi[mt][2], ahi[mt][3], sb + F_W2H + off);
                LDSM_X4(alo[mt][0], alo[mt][1], alo[mt][2], alo[mt][3], sb + F_W2L + off);
            }
            const uint32_t bc = (uint32_t)(k0 + 8 * ((lid >> 3) & 1));
#pragma unroll
            for (int np = 0; np < 2; np++) {
                const uint32_t off = (nbase + np * 16 + bq) * 272 + bc * 2;
                uint32_t bh[4], bl[4];
                LDSM_X4(bh[0], bh[1], bh[2], bh[3], sb + F_HH + off);
                LDSM_X4(bl[0], bl[1], bl[2], bl[3], sb + F_HL + off);
#pragma unroll
                for (int mt = 0; mt < 2; mt++) {
                    MMA_BF16(acc2[mt][2 * np],     ahi[mt], bh[0], bh[1]);
                    MMA_BF16(acc2[mt][2 * np],     ahi[mt], bl[0], bl[1]);
                    MMA_BF16(acc2[mt][2 * np],     alo[mt], bh[0], bh[1]);
                    MMA_BF16(acc2[mt][2 * np + 1], ahi[mt], bh[2], bh[3]);
                    MMA_BF16(acc2[mt][2 * np + 1], ahi[mt], bl[2], bl[3]);
                    MMA_BF16(acc2[mt][2 * np + 1], alo[mt], bh[2], bh[3]);
                }
            }
        }
        __syncthreads();

        {
            float* Dsm = (float*)(smem + F_D);
#pragma unroll
            for (int mt = 0; mt < 2; mt++) {
                const int m = mbase0 + mt * 16 + mo;
#pragma unroll
                for (int nt = 0; nt < 4; nt++) {
                    const int n = nbase + nt * 8 + no;
                    Dsm[n * 132 + m]           = acc2[mt][nt][0];
                    Dsm[(n + 1) * 132 + m]     = acc2[mt][nt][1];
                    Dsm[n * 132 + m + 8]       = acc2[mt][nt][2];
                    Dsm[(n + 1) * 132 + m + 8] = acc2[mt][nt][3];
                }
            }
        }
        __syncthreads();

        {
            const float* Dsm = (const float*)(smem + F_D);
            const float* bp  = (const float*)(smem + F_B2);
            const int s  = tid & 127;
            const int oh = (tid >> 7) * 32;
            const long long gs = tbase + s;
            if (gs < nsamp) {
                float* op = out + gs * 128 + oh;
                const float* dp = Dsm + s * 132 + oh;
#pragma unroll
                for (int i = 0; i < 32; i += 4) {
                    float4 v = *(const float4*)(dp + i);
                    v.x += bp[oh + i];     v.y += bp[oh + i + 1];
                    v.z += bp[oh + i + 2]; v.w += bp[oh + i + 3];
                    *(float4*)(op + i) = v;
                }
            }
        }
    }
}

extern "C" void kernel_launch(void* const* d_in, const int* in_sizes, int n_in,
                              void* d_out, int out_size)
{
    const float* x   = (const float*)d_in[0];
    const float* c1w = (const float*)d_in[1];
    const float* c1b = (const float*)d_in[2];
    const float* c2w = (const float*)d_in[3];
    const float* c2b = (const float*)d_in[4];
    const float* w1  = (const float*)d_in[5];
    const float* b1  = (const float*)d_in[6];
    const float* w2  = (const float*)d_in[7];
    const float* b2  = (const float*)d_in[8];
    float* out = (float*)d_out;

    const int nsamp = in_sizes[0] / 128;
    const int sblocks = (nsamp + 127) / 128;

    cudaFuncSetAttribute(conv1_kernel, cudaFuncAttributeMaxDynamicSharedMemorySize, A1_SMEM);
    cudaFuncSetAttribute(head_kernel,  cudaFuncAttributeMaxDynamicSharedMemorySize, FK_SMEM);

    conv1_kernel<<<sblocks, A1TPB, A1_SMEM>>>(x, c1w, c1b, nsamp);
    conv2_kernel<<<sblocks, A2TPB>>>(c2w, c2b, nsamp);

    const int ntiles = (nsamp + 127) / 128;
    const int blocks = (ntiles < 148) ? ntiles : 148;
    head_kernel<<<blocks, FK_TPB, FK_SMEM>>>(w1, b1, w2, b2, out, nsamp, ntiles);
}

// round 17
// speedup vs baseline: 1.7089x; 1.0297x over previous
#include <cuda_runtime.h>
#include <cuda_bf16.h>
#include <cstdint>

typedef unsigned long long u64;

#define NSMAX 131072
__device__ float g_c1[108 * NSMAX];   // conv1+pool output [ch*36+y*6+x][sample]
__device__ float g_p2[54 * NSMAX];    // conv2+pool output [k][sample]

__device__ __forceinline__ u64 dup2(float a) {
    u64 r; asm("mov.b64 %0, {%1, %1};" : "=l"(r) : "r"(__float_as_uint(a))); return r;
}
__device__ __forceinline__ u64 pack2(float lo, float hi) {
    u64 r; asm("mov.b64 %0, {%1, %2};" : "=l"(r) : "r"(__float_as_uint(lo)), "r"(__float_as_uint(hi))); return r;
}
__device__ __forceinline__ void fma2(u64& acc, u64 a, u64 b) {
    asm("fma.rn.f32x2 %0, %1, %2, %0;" : "+l"(acc) : "l"(a), "l"(b));
}
__device__ __forceinline__ float2 unpack2(u64 v) {
    unsigned lo, hi; asm("mov.b64 {%0, %1}, %2;" : "=r"(lo), "=r"(hi) : "l"(v));
    return make_float2(__uint_as_float(lo), __uint_as_float(hi));
}

// ================================================================
// Kernel A1: conv1 (1->3, 3x3 pad1, 12x12) + maxpool2 + relu -> g_c1
// 128 thr / 128 samples; x in smem; padded r[4][14]  (round-12, 44.2us)
// ================================================================
#define A1TPB 128
#define A1_XS 129
#define A1_SMEM (128 * A1_XS * 4)

__global__ void __launch_bounds__(A1TPB, 3)
conv1_kernel(const float* __restrict__ x,
             const float* __restrict__ c1w, const float* __restrict__ c1b, int nsamp)
{
    extern __shared__ float sx[];
    __shared__ float ws[32];
    const int tid = threadIdx.x;
    if (tid < 27) ws[tid] = c1w[tid];
    if (tid < 3)  ws[27 + tid] = c1b[tid];

    const long long base = (long long)blockIdx.x * A1TPB;

    for (int i = tid; i < 128 * 32; i += A1TPB) {
        const int row = i >> 5, q = (i & 31) * 4;
        const long long s = base + row;
        float4 v = make_float4(0.f, 0.f, 0.f, 0.f);
        if (s < nsamp) v = *(const float4*)(x + s * 128 + q);
        float* d = sx + row * A1_XS + q;
        d[0] = v.x; d[1] = v.y; d[2] = v.z; d[3] = v.w;
    }
    __syncthreads();

    const long long s = base + tid;
    if (s >= nsamp) return;
    const float* xp = sx + tid * A1_XS;

    float W[27];
#pragma unroll
    for (int i = 0; i < 27; i++) W[i] = ws[i];
    const float B0 = ws[27], B1 = ws[28], B2 = ws[29];

#pragma unroll
    for (int py = 0; py < 6; py++) {
        float r[4][14];            // padded: index 0 and 13 are zero
#pragma unroll
        for (int j = 0; j < 4; j++) {
            const int rr = 2 * py - 1 + j;
            r[j][0] = 0.0f; r[j][13] = 0.0f;
            if (rr < 0 || rr >= 11) {
#pragma unroll
                for (int c = 0; c < 12; c++) r[j][1 + c] = 0.0f;
            } else if (rr == 10) {
#pragma unroll
                for (int c = 0; c < 8; c++) r[j][1 + c] = xp[120 + c];
                r[j][9] = 0.0f; r[j][10] = 0.0f; r[j][11] = 0.0f; r[j][12] = 0.0f;
            } else {
#pragma unroll
                for (int c = 0; c < 12; c++) r[j][1 + c] = xp[12 * rr + c];
            }
        }
#pragma unroll
        for (int oc = 0; oc < 3; oc++) {
            float v0[12], v1[12];
#pragma unroll
            for (int cx = 0; cx < 12; cx++) {
                float a0 = 0.0f, a1 = 0.0f;
#pragma unroll
                for (int ky = 0; ky < 3; ky++) {
#pragma unroll
                    for (int kx = 0; kx < 3; kx++) {
                        const float w = W[oc * 9 + ky * 3 + kx];
                        a0 = fmaf(w, r[ky][cx + kx],     a0);
                        a1 = fmaf(w, r[ky + 1][cx + kx], a1);
                    }
                }
                v0[cx] = a0; v1[cx] = a1;
            }
            const float bb = (oc == 0) ? B0 : ((oc == 1) ? B1 : B2);
#pragma unroll
            for (int px = 0; px < 6; px++) {
                float m = fmaxf(fmaxf(v0[2 * px], v0[2 * px + 1]),
                                fmaxf(v1[2 * px], v1[2 * px + 1]));
                g_c1[(long long)(oc * 36 + py * 6 + px) * NSMAX + s] = fmaxf(m + bb, 0.0f);
            }
        }
    }
}

// ================================================================
// Kernel A2: conv2 (3->6, 3x3 pad1, 6x6) + maxpool2 + relu -> g_p2
// 128 thr, padded pcp (round-12 version)
// ================================================================
#define A2TPB 128
__global__ void __launch_bounds__(A2TPB)
conv2_kernel(const float* __restrict__ c2w, const float* __restrict__ c2b, int nsamp)
{
    __shared__ float ws[168];
    const int tid = threadIdx.x;
    for (int i = tid; i < 162; i += A2TPB) ws[i] = c2w[i];
    for (int i = tid; i < 6;   i += A2TPB) ws[162 + i] = c2b[i];
    __syncthreads();

    const long long s = (long long)blockIdx.x * A2TPB + tid;
    if (s >= nsamp) return;

#pragma unroll
    for (int py = 0; py < 3; py++) {
        u64 acc[6][3][2];
#pragma unroll
        for (int oc = 0; oc < 6; oc++)
#pragma unroll
            for (int px = 0; px < 3; px++) { acc[oc][px][0] = 0ull; acc[oc][px][1] = 0ull; }

#pragma unroll
        for (int ic = 0; ic < 3; ic++) {
            float rw[4][6];
#pragma unroll
            for (int j = 0; j < 4; j++) {
                const int y = 2 * py - 1 + j;
                if (y < 0 || y > 5) {
#pragma unroll
                    for (int ix = 0; ix < 6; ix++) rw[j][ix] = 0.0f;
                } else {
#pragma unroll
                    for (int ix = 0; ix < 6; ix++)
                        rw[j][ix] = g_c1[(long long)(ic * 36 + y * 6 + ix) * NSMAX + s];
                }
            }
            u64 pcp[3][8];
#pragma unroll
            for (int j = 0; j < 3; j++) {
                pcp[j][0] = 0ull; pcp[j][7] = 0ull;
#pragma unroll
                for (int ix = 0; ix < 6; ix++)
                    pcp[j][1 + ix] = pack2(rw[j][ix], rw[j + 1][ix]);
            }

#pragma unroll
            for (int oc = 0; oc < 6; oc++) {
#pragma unroll
                for (int ky = 0; ky < 3; ky++) {
#pragma unroll
                    for (int kx = 0; kx < 3; kx++) {
                        const u64 wd = dup2(ws[oc * 27 + ic * 9 + ky * 3 + kx]);
#pragma unroll
                        for (int px = 0; px < 3; px++) {
                            fma2(acc[oc][px][0], wd, pcp[ky][2 * px + kx]);
                            fma2(acc[oc][px][1], wd, pcp[ky][2 * px + kx + 1]);
                        }
                    }
                }
            }
        }
#pragma unroll
        for (int oc = 0; oc < 6; oc++) {
            const float bb = ws[162 + oc];
#pragma unroll
            for (int px = 0; px < 3; px++) {
                float2 v0 = unpack2(acc[oc][px][0]), v1 = unpack2(acc[oc][px][1]);
                float m = fmaxf(fmaxf(v0.x, v0.y), fmaxf(v1.x, v1.y));
                g_p2[(long long)(oc * 9 + py * 3 + px) * NSMAX + s] = fmaxf(m + bb, 0.0f);
            }
        }
    }
}

// ================================================================
// Kernel F: fused fc1+relu+out, chained mma.sync bf16 3-term split
// 512 threads; warp tile m32 x n32; MMAs reordered TERM-MAJOR so each
// accumulator's chained MMAs are separated by 3 independent ones.
// ================================================================
#define FK_TPB  512
#define F_B1   0
#define F_B2   512
#define F_W1H  1024
#define F_W1L  19456
#define F_W2H  37888
#define F_W2L  72704
#define F_P2H  107520
#define F_P2L  125952
#define F_HH   144384
#define F_HL   179200
#define F_D    144384
#define FK_SMEM 214016

#define LDSM_X4(r0, r1, r2, r3, addr) \
    asm volatile("ldmatrix.sync.aligned.m8n8.x4.shared.b16 {%0,%1,%2,%3}, [%4];" \
        : "=r"(r0), "=r"(r1), "=r"(r2), "=r"(r3) : "r"(addr))

#define MMA_BF16(c, a, b0, b1) \
    asm volatile("mma.sync.aligned.m16n8k16.row.col.f32.bf16.bf16.f32 " \
        "{%0,%1,%2,%3}, {%4,%5,%6,%7}, {%8,%9}, {%0,%1,%2,%3};" \
        : "+f"((c)[0]), "+f"((c)[1]), "+f"((c)[2]), "+f"((c)[3]) \
        : "r"((a)[0]), "r"((a)[1]), "r"((a)[2]), "r"((a)[3]), "r"(b0), "r"(b1))

__device__ __forceinline__ uint32_t smem_u32(const void* p) {
    uint32_t a;
    asm("{ .reg .u64 t; cvta.to.shared.u64 t, %1; cvt.u32.u64 %0, t; }" : "=r"(a) : "l"(p));
    return a;
}
__device__ __forceinline__ void bf16split(float f0, float f1, unsigned& hi, unsigned& lo) {
    asm("cvt.rn.bf16x2.f32 %0, %1, %2;" : "=r"(hi) : "f"(f1), "f"(f0));
    const float h0 = __uint_as_float(hi << 16);
    const float h1 = __uint_as_float(hi & 0xFFFF0000u);
    const float r0 = f0 - h0, r1 = f1 - h1;
    asm("cvt.rn.bf16x2.f32 %0, %1, %2;" : "=r"(lo) : "f"(r1), "f"(r0));
}
__device__ __forceinline__ void bf16split1(float v, unsigned short& hi, unsigned short& lo) {
    __nv_bfloat16 h = __float2bfloat16(v);
    float r = v - __bfloat162float(h);
    __nv_bfloat16 l = __float2bfloat16(r);
    hi = *(unsigned short*)&h;
    lo = *(unsigned short*)&l;
}

__global__ void __launch_bounds__(FK_TPB, 1)
head_kernel(const float* __restrict__ w1, const float* __restrict__ b1,
            const float* __restrict__ w2, const float* __restrict__ b2,
            float* __restrict__ out, int nsamp, int ntiles)
{
    extern __shared__ char smem[];
    const uint32_t sb = smem_u32(smem);
    const int tid = threadIdx.x;
    const int wid = tid >> 5, lid = tid & 31;

    if (tid < 128) { ((float*)(smem + F_B1))[tid] = b1[tid];
                     ((float*)(smem + F_B2))[tid] = b2[tid]; }
    for (int i = tid; i < 9216; i += FK_TPB) {
        ((uint32_t*)(smem + F_W1H))[i] = 0u;
        ((uint32_t*)(smem + F_P2H))[i] = 0u;
    }
    __syncthreads();
    if (tid < 128) {
        const int o = tid;
        const float* wr = w1 + o * 54;
        char* ah = smem + F_W1H + o * 144;
        char* al = smem + F_W1L + o * 144;
        for (int i = 0; i < 54; i += 2) {
            const float2 f = *(const float2*)(wr + i);
            unsigned h, l;
            bf16split(f.x, f.y, h, l);
            *(unsigned*)(ah + i * 2) = h;
            *(unsigned*)(al + i * 2) = l;
        }
    }
    {
        const int o  = tid & 127;
        const int kq = (tid >> 7) * 32;
        const float* wr = w2 + o * 128 + kq;
        char* ah = smem + F_W2H + o * 272 + kq * 2;
        char* al = smem + F_W2L + o * 272 + kq * 2;
        for (int i = 0; i < 32; i += 4) {
            const float4 f = *(const float4*)(wr + i);
            unsigned h0, l0, h1, l1;
            bf16split(f.x, f.y, h0, l0);
            bf16split(f.z, f.w, h1, l1);
            *(uint2*)(ah + i * 2) = make_uint2(h0, h1);
            *(uint2*)(al + i * 2) = make_uint2(l0, l1);
        }
    }

    const int mgrp = wid & 3;
    const int ngrp = wid >> 2;
    const int mbase0 = mgrp * 32;
    const int nbase  = ngrp * 32;
    const uint32_t ar = (uint32_t)((lid & 7) + 8 * ((lid >> 3) & 1));
    const uint32_t bq = (uint32_t)((lid & 7) + 8 * (lid >> 4));
    const int mo = lid >> 2;
    const int no = 2 * (lid & 3);

    for (int tile = blockIdx.x; tile < ntiles; tile += gridDim.x) {
        const long long tbase = (long long)tile * 128;

        __syncthreads();

        for (int idx = tid; idx < 54 * 32; idx += FK_TPB) {
            const int k = idx >> 5, s4 = (idx & 31) * 4;
            const float4 f = *(const float4*)(g_p2 + (long long)k * NSMAX + tbase + s4);
            unsigned short h, l;
#pragma unroll
            for (int j = 0; j < 4; j++) {
                const float v = (j == 0) ? f.x : (j == 1) ? f.y : (j == 2) ? f.z : f.w;
                bf16split1(v, h, l);
                *(unsigned short*)(smem + F_P2H + (s4 + j) * 144 + k * 2) = h;
                *(unsigned short*)(smem + F_P2L + (s4 + j) * 144 + k * 2) = l;
            }
        }
        __syncthreads();

        // ---- GEMM1: W1 * P2^T (K=64, 3-term, term-major MMA order) ----
        float acc1[2][4][4];
#pragma unroll
        for (int mt = 0; mt < 2; mt++)
#pragma unroll
            for (int nt = 0; nt < 4; nt++)
#pragma unroll
                for (int q = 0; q < 4; q++) acc1[mt][nt][q] = 0.0f;

#pragma unroll
        for (int k0 = 0; k0 < 64; k0 += 16) {
            const uint32_t ac = (uint32_t)(k0 + 8 * (lid >> 4));
            uint32_t ahi[2][4], alo[2][4];
#pragma unroll
            for (int mt = 0; mt < 2; mt++) {
                const uint32_t off = (mbase0 + mt * 16 + ar) * 144 + ac * 2;
                LDSM_X4(ahi[mt][0], ahi[mt][1], ahi[mt][2], ahi[mt][3], sb + F_W1H + off);
                LDSM_X4(alo[mt][0], alo[mt][1], alo[mt][2], alo[mt][3], sb + F_W1L + off);
            }
            const uint32_t bc = (uint32_t)(k0 + 8 * ((lid >> 3) & 1));
#pragma unroll
            for (int np = 0; np < 2; np++) {
                const uint32_t off = (nbase + np * 16 + bq) * 144 + bc * 2;
                uint32_t bh[4], bl[4];
                LDSM_X4(bh[0], bh[1], bh[2], bh[3], sb + F_P2H + off);
                LDSM_X4(bl[0], bl[1], bl[2], bl[3], sb + F_P2L + off);
                // term-major: all hh, then all hl, then all lh (4 accs interleave)
#pragma unroll
                for (int mt = 0; mt < 2; mt++) {
                    MMA_BF16(acc1[mt][2 * np],     ahi[mt], bh[0], bh[1]);
                    MMA_BF16(acc1[mt][2 * np + 1], ahi[mt], bh[2], bh[3]);
                }
#pragma unroll
                for (int mt = 0; mt < 2; mt++) {
                    MMA_BF16(acc1[mt][2 * np],     ahi[mt], bl[0], bl[1]);
                    MMA_BF16(acc1[mt][2 * np + 1], ahi[mt], bl[2], bl[3]);
                }
#pragma unroll
                for (int mt = 0; mt < 2; mt++) {
                    MMA_BF16(acc1[mt][2 * np],     alo[mt], bh[0], bh[1]);
                    MMA_BF16(acc1[mt][2 * np + 1], alo[mt], bh[2], bh[3]);
                }
            }
        }

        {
            const float* bp = (const float*)(smem + F_B1);
#pragma unroll
            for (int mt = 0; mt < 2; mt++) {
                const int m = mbase0 + mt * 16 + mo;
                const float bA = bp[m], bB = bp[m + 8];
#pragma unroll
                for (int nt = 0; nt < 4; nt++) {
                    const int n = nbase + nt * 8 + no;
                    const float v0 = fmaxf(acc1[mt][nt][0] + bA, 0.0f);
                    const float v1 = fmaxf(acc1[mt][nt][1] + bA, 0.0f);
                    const float v2 = fmaxf(acc1[mt][nt][2] + bB, 0.0f);
                    const float v3 = fmaxf(acc1[mt][nt][3] + bB, 0.0f);
                    unsigned short h, l;
                    bf16split1(v0, h, l);
                    *(unsigned short*)(smem + F_HH + n * 272 + m * 2) = h;
                    *(unsigned short*)(smem + F_HL + n * 272 + m * 2) = l;
                    bf16split1(v1, h, l);
                    *(unsigned short*)(smem + F_HH + (n + 1) * 272 + m * 2) = h;
                    *(unsigned short*)(smem + F_HL + (n + 1) * 272 + m * 2) = l;
                    bf16split1(v2, h, l);
                    *(unsigned short*)(smem + F_HH + n * 272 + (m + 8) * 2) = h;
                    *(unsigned short*)(smem + F_HL + n * 272 + (m + 8) * 2) = l;
                    bf16split1(v3, h, l);
                    *(unsigned short*)(smem + F_HH + (n + 1) * 272 + (m + 8) * 2) = h;
                    *(unsigned short*)(smem + F_HL + (n + 1) * 272 + (m + 8) * 2) = l;
                }
            }
        }
        __syncthreads();

        // ---- GEMM2: W2 * H^T (K=128, 3-term, term-major MMA order) ----
        float acc2[2][4][4];
#pragma unroll
        for (int mt = 0; mt < 2; mt++)
#pragma unroll
            for (int nt = 0; nt < 4; nt++)
#pragma unroll
                for (int q = 0; q < 4; q++) acc2[mt][nt][q] = 0.0f;

#pragma unroll
        for (int k0 = 0; k0 < 128; k0 += 16) {
            const uint32_t ac = (uint32_t)(k0 + 8 * (lid >> 4));
            uint32_t ahi[2][4], alo[2][4];
#pragma unroll
            for (int mt = 0; mt < 2; mt++) {
                const uint32_t off = (mbase0 + mt * 16 + ar) * 272 + ac * 2;
                LDSM_X4(ahi[mt][0], ahi[mt][1], ahi[mt][2], ahi[mt][3], sb + F_W2H + off);
                LDSM_X4(alo[mt][0], alo[mt][1], alo[mt][2], alo[mt][3], sb + F_W2L + off);
            }
            const uint32_t bc = (uint32_t)(k0 + 8 * ((lid >> 3) & 1));
#pragma unroll
            for (int np = 0; np < 2; np++) {
                const uint32_t off = (nbase + np * 16 + bq) * 272 + bc * 2;
                uint32_t bh[4], bl[4];
                LDSM_X4(bh[0], bh[1], bh[2], bh[3], sb + F_HH + off);
                LDSM_X4(bl[0], bl[1], bl[2], bl[3], sb + F_HL + off);
#pragma unroll
                for (int mt = 0; mt < 2; mt++) {
                    MMA_BF16(acc2[mt][2 * np],     ahi[mt], bh[0], bh[1]);
                    MMA_BF16(acc2[mt][2 * np + 1], ahi[mt], bh[2], bh[3]);
                }
#pragma unroll
                for (int mt = 0; mt < 2; mt++) {
                    MMA_BF16(acc2[mt][2 * np],     ahi[mt], bl[0], bl[1]);
                    MMA_BF16(acc2[mt][2 * np + 1], ahi[mt], bl[2], bl[3]);
                }
#pragma unroll
                for (int mt = 0; mt < 2; mt++) {
                    MMA_BF16(acc2[mt][2 * np],     alo[mt], bh[0], bh[1]);
                    MMA_BF16(acc2[mt][2 * np + 1], alo[mt], bh[2], bh[3]);
                }
            }
        }
        __syncthreads();

        {
            float* Dsm = (float*)(smem + F_D);
#pragma unroll
            for (int mt = 0; mt < 2; mt++) {
                const int m = mbase0 + mt * 16 + mo;
#pragma unroll
                for (int nt = 0; nt < 4; nt++) {
                    const int n = nbase + nt * 8 + no;
                    Dsm[n * 132 + m]           = acc2[mt][nt][0];
                    Dsm[(n + 1) * 132 + m]     = acc2[mt][nt][1];
                    Dsm[n * 132 + m + 8]       = acc2[mt][nt][2];
                    Dsm[(n + 1) * 132 + m + 8] = acc2[mt][nt][3];
                }
            }
        }
        __syncthreads();

        {
            const float* Dsm = (const float*)(smem + F_D);
            const float* bp  = (const float*)(smem + F_B2);
            const int s  = tid & 127;
            const int oh = (tid >> 7) * 32;
            const long long gs = tbase + s;
            if (gs < nsamp) {
                float* op = out + gs * 128 + oh;
                const float* dp = Dsm + s * 132 + oh;
#pragma unroll
                for (int i = 0; i < 32; i += 4) {
                    float4 v = *(const float4*)(dp + i);
                    v.x += bp[oh + i];     v.y += bp[oh + i + 1];
                    v.z += bp[oh + i + 2]; v.w += bp[oh + i + 3];
                    *(float4*)(op + i) = v;
                }
            }
        }
    }
}

extern "C" void kernel_launch(void* const* d_in, const int* in_sizes, int n_in,
                              void* d_out, int out_size)
{
    const float* x   = (const float*)d_in[0];
    const float* c1w = (const float*)d_in[1];
    const float* c1b = (const float*)d_in[2];
    const float* c2w = (const float*)d_in[3];
    const float* c2b = (const float*)d_in[4];
    const float* w1  = (const float*)d_in[5];
    const float* b1  = (const float*)d_in[6];
    const float* w2  = (const float*)d_in[7];
    const float* b2  = (const float*)d_in[8];
    float* out = (float*)d_out;

    const int nsamp = in_sizes[0] / 128;

    cudaFuncSetAttribute(conv1_kernel, cudaFuncAttributeMaxDynamicSharedMemorySize, A1_SMEM);
    cudaFuncSetAttribute(head_kernel,  cudaFuncAttributeMaxDynamicSharedMemorySize, FK_SMEM);

    conv1_kernel<<<(nsamp + A1TPB - 1) / A1TPB, A1TPB, A1_SMEM>>>(x, c1w, c1b, nsamp);
    conv2_kernel<<<(nsamp + A2TPB - 1) / A2TPB, A2TPB>>>(c2w, c2b, nsamp);

    const int ntiles = (nsamp + 127) / 128;
    const int blocks = (ntiles < 148) ? ntiles : 148;
    head_kernel<<<blocks, FK_TPB, FK_SMEM>>>(w1, b1, w2, b2, out, nsamp, ntiles);
}